// round 7
// baseline (speedup 1.0000x reference)
#include <cuda_runtime.h>
#include <math.h>

// Preisach hysteresis:
//   state row j = prefix of +1 of length c_j, then -1 (within lower triangle).
//   up-step h:   rows with x[j] < h  -> c_j = j+1
//   down-step h: all rows            -> c_j = min(c_j, K), K = #{k: x[k] <= h}
//   b[t] = (sum_j (2*P_j(c_j) - RowTot_j)) / 32896 * scale + offset
// R6: k1 row-scan made single-pass — element-level int quantization lets each
//     warp front-load 8 floats/lane (MLP=8), do one blocked int scan + one
//     SHFL scan. Removes the 8-batch carry/LDG serial chain.

#define NN 256
#define TT 2000
#define LSIZE 33152          // sum_j (j+2)
#define CHUNK 25
#define NCHUNK 80
#define QSCALE 8192.0f

__device__ int g_Li[LSIZE];        // quantized row-local prefix sums of softplus(density)
__device__ int g_RowTotI[NN];
__device__ int g_meta[TT];         // -1 up, -2 flat, else K (down)
__device__ __align__(16) int g_fvT[NN * NCHUNK];   // [row][chunk] transfer functions
__device__ int g_centry[NCHUNK * NN];              // [chunk][row] entry states
__device__ int g_TotalI;

__device__ __forceinline__ float xval(int i) {
    // replicate jnp.linspace(0,1,256) in f32: i * fl(1/255), endpoint exact
    return (i == NN - 1) ? 1.0f : (float)i * (1.0f / 255.0f);
}
__device__ __forceinline__ float softplusf(float v) {
    return fmaxf(v, 0.0f) + log1pf(expf(-fabsf(v)));
}

// KA: fused row prefix sums (blocks 0..15, one warp per row, single-pass) +
//     meta + chunk transfer compose (blocks 16..95).
__global__ void kA_fused(const float* __restrict__ raw, const float* __restrict__ h) {
    if (blockIdx.x < 16) {
        // ---- per-row prefix sums, one warp per row, MLP=8 single pass ----
        int warp = (blockIdx.x * 512 + threadIdx.x) >> 5;
        int lane = threadIdx.x & 31;
        int j  = warp;                       // row index 0..255
        int sj = j * (j + 1) / 2;
        int oj = sj + j;
        int n  = j + 1;

        // each lane owns elements [8*lane, 8*lane+8)
        int base = lane * 8;
        float v[8];
        #pragma unroll
        for (int k = 0; k < 8; k++) {
            int idx = base + k;
            v[k] = (idx < n) ? raw[sj + idx] : 0.0f;   // 8 independent LDGs
        }
        int loc[8];
        int run = 0;
        #pragma unroll
        for (int k = 0; k < 8; k++) {
            int idx = base + k;
            int q = (idx < n) ? __float2int_rn(softplusf(v[k]) * QSCALE) : 0;
            run += q;
            loc[k] = run;                    // inclusive local prefix (int, exact)
        }
        // exclusive warp scan of lane totals
        int excl = run;
        #pragma unroll
        for (int d = 1; d < 32; d <<= 1) {
            int t = __shfl_up_sync(0xffffffffu, excl, d);
            if (lane >= d) excl += t;
        }
        excl -= run;                          // exclusive prefix for this lane

        if (lane == 0) g_Li[oj] = 0;
        #pragma unroll
        for (int k = 0; k < 8; k++) {
            int idx = base + k;
            if (idx < n) g_Li[oj + 1 + idx] = excl + loc[k];
        }
        if (lane == 31) g_RowTotI[j] = excl + run;   // exact row total
    } else {
        // ---- per-step meta + per-(chunk,row) transfer compose ----
        __shared__ int   sm[CHUNK];
        __shared__ float shh[CHUNK];
        int ci = blockIdx.x - 16;
        int j  = threadIdx.x;
        int t0 = ci * CHUNK;

        if (j < CHUNK) {
            int t = t0 + j;
            float hp = (t == 0) ? 0.0f : h[t - 1];
            float hc = h[t];
            int m;
            if (hc > hp) {
                m = -1;
            } else if (hc < hp) {
                int K = 0;
                #pragma unroll 8
                for (int k = 0; k < NN; k++) K += (xval(k) <= hc) ? 1 : 0;
                m = K;
            } else {
                m = -2;
            }
            sm[j] = m; shh[j] = hc;
            g_meta[t] = m;
        }
        __syncthreads();
        if (j < NN) {
            float xj = xval(j);
            bool isC = false;
            int v = 0, m = 511;
            #pragma unroll
            for (int s = 0; s < CHUNK; s++) {
                int mt = sm[s];
                if (mt == -1) {
                    if (xj < shh[s]) { isC = true; v = j + 1; }
                } else if (mt >= 0) {
                    if (isC) v = min(v, mt); else m = min(m, mt);
                }
            }
            g_fvT[j * NCHUNK + ci] = isC ? (512 + v) : m;
        }
    }
}

// KB: per-row scan over chunk functions -> entry state per chunk; Total reduce.
// All 80 values prefetched as 20 int4 (MLP~20), scan fully unrolled in regs.
__global__ void kB_scan() {
    int j = threadIdx.x;
    const int4* fv = reinterpret_cast<const int4*>(&g_fvT[j * NCHUNK]);
    int f[NCHUNK];
    #pragma unroll
    for (int b = 0; b < NCHUNK / 4; b++) {
        int4 t = fv[b];
        f[4 * b + 0] = t.x; f[4 * b + 1] = t.y;
        f[4 * b + 2] = t.z; f[4 * b + 3] = t.w;
    }
    int c = 0;
    #pragma unroll
    for (int i = 0; i < NCHUNK; i++) {
        g_centry[i * NN + j] = c;          // coalesced across threads
        int fs = f[i];
        c = (fs >= 512) ? (fs - 512) : min(c, fs);
    }
    __shared__ int red[NN];
    red[j] = g_RowTotI[j];
    __syncthreads();
    for (int off = 128; off > 0; off >>= 1) {
        if (j < off) red[j] += red[j + off];
        __syncthreads();
    }
    if (j == 0) g_TotalI = red[0];
}

// KC: expand — one warp per output step. Replay chunk-local prefix in
// registers, then 8 parallel Li lookups + REDUX. 8 warps/CTA, 250 CTAs.
__global__ void kC_expand(const float* __restrict__ h,
                          const float* __restrict__ offset,
                          const float* __restrict__ scale,
                          float* __restrict__ out) {
    __shared__ int   sm[40];
    __shared__ float shh[40];
    int blockBase = blockIdx.x * 8;              // first step of this CTA
    int cs = (blockBase / CHUNK) * CHUNK;        // chunk start of first warp
    int need = blockBase + 8 - cs;               // <= 32
    int tid = threadIdx.x;
    if (tid < need) { sm[tid] = g_meta[cs + tid]; shh[tid] = h[cs + tid]; }
    __syncthreads();

    int warpId = tid >> 5;
    int lane   = tid & 31;
    int t  = blockBase + warpId;                 // this warp's output step
    int ci = t / CHUNK;
    int t0 = ci * CHUNK;
    int lu0 = t0 - cs;                           // smem offset of chunk start
    int nsteps = t - t0 + 1;                     // steps to replay (1..25)

    int   c[8], oj[8];
    float xq[8];
    #pragma unroll
    for (int q = 0; q < 8; q++) {
        int j = lane + 32 * q;
        oj[q] = j * (j + 3) / 2;
        xq[q] = xval(j);
        c[q]  = g_centry[ci * NN + j];
    }

    for (int u = 0; u < nsteps; u++) {
        int   mt = sm[lu0 + u];
        float hc = shh[lu0 + u];
        if (mt == -1) {
            #pragma unroll
            for (int q = 0; q < 8; q++) {
                int j = lane + 32 * q;
                if (xq[q] < hc) c[q] = j + 1;
            }
        } else if (mt >= 0) {
            #pragma unroll
            for (int q = 0; q < 8; q++) c[q] = min(c[q], mt);
        }
    }

    // 8 independent lookups, issued together (MLP=8)
    int rv[8];
    #pragma unroll
    for (int q = 0; q < 8; q++) rv[q] = g_Li[oj[q] + c[q]];

    int s8 = ((rv[0] + rv[1]) + (rv[2] + rv[3])) +
             ((rv[4] + rv[5]) + (rv[6] + rv[7]));
    int tot = __reduce_add_sync(0xffffffffu, s8);

    if (lane == 0) {
        float numer = (float)(2 * tot - g_TotalI) * (1.0f / QSCALE);
        out[t] = numer * (1.0f / 32896.0f) * scale[0] + offset[0];
    }
}

extern "C" void kernel_launch(void* const* d_in, const int* in_sizes, int n_in,
                              void* d_out, int out_size) {
    const float* h      = (const float*)d_in[0];
    const float* raw    = (const float*)d_in[1];
    const float* offset = (const float*)d_in[2];
    const float* scale  = (const float*)d_in[3];
    float* out = (float*)d_out;

    kA_fused<<<96, 512>>>(raw, h);
    kB_scan<<<1, 256>>>();
    kC_expand<<<TT / 8, 256>>>(h, offset, scale, out);
}